// round 6
// baseline (speedup 1.0000x reference)
#include <cuda_runtime.h>
#include <math.h>

// Problem constants
#define NT    65536          // N*T rows
#define DD    256            // feature dim
#define MM    512            // codebook size
#define NTD   16777216       // N*T*D

#define ROWS_PER_BLOCK 64
#define NBLOCKS (NT / ROWS_PER_BLOCK)   // 1024
#define CODES_PER_TILE 128              // 4 code tiles
#define K_CHUNK 64                      // 4 k chunks

// smem layout (floats)
#define XS_ROW 68                       // 64 rows + pad
#define XS_FLOATS (DD * XS_ROW)         // 17408 floats
#define ES_ROW 132                      // 128 codes + pad
#define ES_FLOATS (K_CHUNK * ES_ROW)    // 8448 floats
#define SMEM_FLOATS (XS_FLOATS + ES_FLOATS + MM + 64 /*rowidx*/ + 64 /*sx*/ + 16)
#define SMEM_BYTES (SMEM_FLOATS * 4)

// Device scratch (no allocation allowed)
__device__ float g_embnT[DD * MM];      // normalized codebook, transposed [k][j]
__device__ float g_c[MM];               // ||emb_norm_j||^2 (ref-rounding emulated)
__device__ float g_loss_part[NBLOCKS];  // deterministic per-block loss partials
__device__ int   g_hist[MM];            // index histogram

// XLA-style warp reduce over 256 values stored in shared: lane l takes
// elements {4l..4l+3, 128+4l..128+4l+3} sequentially, then pairwise xor tree.
__device__ __forceinline__ float warp_reduce256(const float* v, int lane) {
    float s = 0.0f;
#pragma unroll
    for (int c = 0; c < 4; c++) s = __fadd_rn(s, v[4 * lane + c]);
#pragma unroll
    for (int c = 0; c < 4; c++) s = __fadd_rn(s, v[128 + 4 * lane + c]);
#pragma unroll
    for (int off = 16; off > 0; off >>= 1)
        s = __fadd_rn(s, __shfl_xor_sync(0xffffffffu, s, off));
    return s;
}

// ---------------------------------------------------------------------------
// Prep: row-normalize codebook (IEEE div), build transposed copy + c_j,
// zero histogram. grid = 512 blocks, 256 threads.
// ---------------------------------------------------------------------------
__global__ void vq_prep_kernel(const float* __restrict__ emb) {
    int j = blockIdx.x;
    int t = threadIdx.x;
    __shared__ float sq[256];
    __shared__ float norm_s;

    float v = emb[j * DD + t];
    sq[t] = __fmul_rn(v, v);               // rounded squares (no fma fusion)
    __syncthreads();
    if (t < 32) {
        float s = warp_reduce256(sq, t);
        if (t == 0) norm_s = sqrtf(s);     // IEEE sqrt, matches XLA
    }
    __syncthreads();

    float e = v / __fadd_rn(norm_s, 1e-4f);   // IEEE division, matches XLA
    g_embnT[t * MM + j] = e;

    sq[t] = __fmul_rn(e, e);
    __syncthreads();
    if (t < 32) {
        float s = warp_reduce256(sq, t);
        if (t == 0) { g_c[j] = s; g_hist[j] = 0; }
    }
}

// ---------------------------------------------------------------------------
// Main: per block: 64 rows x 512 codes argmin + gather + loss + hist
// grid = 1024 blocks, 256 threads, dynamic smem
// ---------------------------------------------------------------------------
__global__ void __launch_bounds__(256, 2)
vq_main_kernel(const float* __restrict__ x,
               const float* __restrict__ emb,
               float* __restrict__ out) {
    extern __shared__ float sm[];
    float* x_s    = sm;                       // [256][68]  transposed x tile
    float* e_s    = sm + XS_FLOATS;           // [64][132]  e chunk; reused
    float* c_s    = e_s + ES_FLOATS;          // [512]
    int*   rowidx = (int*)(c_s + MM);         // [64]
    float* sx_s   = (float*)(rowidx + 64);    // [64]  per-row ||x||^2
    float* lred   = sx_s + 64;                // [8]

    const int tid = threadIdx.x;
    const int b   = blockIdx.x;
    const long r0 = (long)b * ROWS_PER_BLOCK;

    // load c_j
    for (int i = tid; i < MM; i += 256) c_s[i] = g_c[i];

    // load x tile, transpose into smem: x_s[k][row]
    const float4* xg = (const float4*)(x + r0 * DD);
#pragma unroll
    for (int i = 0; i < 16; i++) {
        int v   = tid + i * 256;      // float4 index, 0..4095
        int row = v >> 6;             // 64 float4 per row
        int kq  = v & 63;
        float4 val = xg[v];
        int k = kq * 4;
        x_s[(k + 0) * XS_ROW + row] = val.x;
        x_s[(k + 1) * XS_ROW + row] = val.y;
        x_s[(k + 2) * XS_ROW + row] = val.z;
        x_s[(k + 3) * XS_ROW + row] = val.w;
    }
    __syncthreads();

    // per-row sx = sum(x^2) with ref-emulating rounding + XLA-style tree
    {
        int w = tid >> 5, l = tid & 31;
#pragma unroll
        for (int rr = 0; rr < 8; rr++) {
            int row = w * 8 + rr;
            float s = 0.0f;
#pragma unroll
            for (int c = 0; c < 4; c++) {
                float v = x_s[(4 * l + c) * XS_ROW + row];
                s = __fadd_rn(s, __fmul_rn(v, v));
            }
#pragma unroll
            for (int c = 0; c < 4; c++) {
                float v = x_s[(128 + 4 * l + c) * XS_ROW + row];
                s = __fadd_rn(s, __fmul_rn(v, v));
            }
#pragma unroll
            for (int off = 16; off > 0; off >>= 1)
                s = __fadd_rn(s, __shfl_xor_sync(0xffffffffu, s, off));
            if (l == 0) sx_s[row] = s;
        }
    }
    __syncthreads();

    const int tx = tid & 31;   // code group: codes tx*4 .. tx*4+3 within tile
    const int ty = tid >> 5;   // row group: rows ty*8 .. ty*8+7

    float bv[8];
    int   bi[8];
#pragma unroll
    for (int i = 0; i < 8; i++) { bv[i] = INFINITY; bi[i] = 0; }

    for (int ct = 0; ct < MM / CODES_PER_TILE; ct++) {
        float acc[8][4];
#pragma unroll
        for (int i = 0; i < 8; i++)
#pragma unroll
            for (int j = 0; j < 4; j++) acc[i][j] = 0.0f;

        for (int kt = 0; kt < DD / K_CHUNK; kt++) {
            __syncthreads();   // previous e_s users done
            // stage e chunk: [64 k][128 codes]
#pragma unroll
            for (int i = 0; i < 8; i++) {
                int v  = tid + i * 256;       // float4 index
                int kk = v >> 5;
                int jq = v & 31;
                float4 val = *(const float4*)&g_embnT[(kt * K_CHUNK + kk) * MM
                                                      + ct * CODES_PER_TILE + jq * 4];
                *(float4*)&e_s[kk * ES_ROW + jq * 4] = val;
            }
            __syncthreads();

#pragma unroll 4
            for (int k = 0; k < K_CHUNK; k++) {
                const float* xr = &x_s[(kt * K_CHUNK + k) * XS_ROW + ty * 8];
                float4 xa = *(const float4*)(xr);
                float4 xb = *(const float4*)(xr + 4);
                float4 ef = *(const float4*)&e_s[k * ES_ROW + tx * 4];
                float xv[8] = {xa.x, xa.y, xa.z, xa.w, xb.x, xb.y, xb.z, xb.w};
                float ev[4] = {ef.x, ef.y, ef.z, ef.w};
#pragma unroll
                for (int i = 0; i < 8; i++)
#pragma unroll
                    for (int j = 0; j < 4; j++)
                        acc[i][j] = fmaf(xv[i], ev[j], acc[i][j]);
            }
        }

        // fold into running best using the REFERENCE-rounded metric:
        // m = fl( fl(c_j + sx) - 2*s ); argmin, lowest index wins ties
#pragma unroll
        for (int j = 0; j < 4; j++) {
            int code = ct * CODES_PER_TILE + tx * 4 + j;
            float c = c_s[code];
#pragma unroll
            for (int i = 0; i < 8; i++) {
                float t_ = __fadd_rn(c, sx_s[ty * 8 + i]);
                float m  = __fadd_rn(t_, -2.0f * acc[i][j]);  // 2*s exact
                if (m < bv[i]) { bv[i] = m; bi[i] = code; }
            }
        }
    }

    // cross-thread argmin reduce, reusing e_s space
    __syncthreads();
    float* red_v = e_s;                 // [64][32]
    int*   red_i = (int*)(e_s + 64 * 32);
#pragma unroll
    for (int i = 0; i < 8; i++) {
        int row = ty * 8 + i;
        red_v[row * 32 + tx] = bv[i];
        red_i[row * 32 + tx] = bi[i];
    }
    __syncthreads();
    if (tid < 64) {
        int row = tid;
        float best = red_v[row * 32];
        int   idx  = red_i[row * 32];
        for (int t2 = 1; t2 < 32; t2++) {
            float v = red_v[row * 32 + t2];
            int  ii = red_i[row * 32 + t2];
            if (v < best || (v == best && ii < idx)) { best = v; idx = ii; }
        }
        rowidx[row] = idx;
        atomicAdd(&g_hist[idx], 1);
    }
    __syncthreads();

    // gather codewords; emulate straight-through arithmetic exactly:
    // out = fl( fl(x + fl(q - x)) + q ) * 0.5
    float lsum = 0.0f;
    {
        int row   = tid >> 2;          // 4 threads per row
        int kbase = (tid & 3) * 64;
        int idx   = rowidx[row];
        const float4* eq = (const float4*)(emb + (long)idx * DD + kbase);
        float4*       og = (float4*)(out + (r0 + row) * DD + kbase);
#pragma unroll
        for (int i = 0; i < 16; i++) {
            float4 q = eq[i];
            int k = kbase + i * 4;
            float xv0 = x_s[(k + 0) * XS_ROW + row];
            float xv1 = x_s[(k + 1) * XS_ROW + row];
            float xv2 = x_s[(k + 2) * XS_ROW + row];
            float xv3 = x_s[(k + 3) * XS_ROW + row];

            float4 o;
            o.x = __fmul_rn(__fadd_rn(__fadd_rn(xv0, __fadd_rn(q.x, -xv0)), q.x), 0.5f);
            o.y = __fmul_rn(__fadd_rn(__fadd_rn(xv1, __fadd_rn(q.y, -xv1)), q.y), 0.5f);
            o.z = __fmul_rn(__fadd_rn(__fadd_rn(xv2, __fadd_rn(q.z, -xv2)), q.z), 0.5f);
            o.w = __fmul_rn(__fadd_rn(__fadd_rn(xv3, __fadd_rn(q.w, -xv3)), q.w), 0.5f);
            og[i] = o;

            float d0 = __fadd_rn(xv0, -q.x);
            float d1 = __fadd_rn(xv1, -q.y);
            float d2 = __fadd_rn(xv2, -q.z);
            float d3 = __fadd_rn(xv3, -q.w);
            lsum += d0 * d0 + d1 * d1 + d2 * d2 + d3 * d3;
        }
    }
    // deterministic block reduce of lsum
#pragma unroll
    for (int off = 16; off > 0; off >>= 1)
        lsum += __shfl_down_sync(0xffffffffu, lsum, off);
    if ((tid & 31) == 0) lred[tid >> 5] = lsum;
    __syncthreads();
    if (tid == 0) {
        float tot = 0.0f;
        for (int w = 0; w < 8; w++) tot += lred[w];
        g_loss_part[b] = tot;
    }
}

// ---------------------------------------------------------------------------
// Finalize: loss mean + perplexity -> out tail. 1 block x 512 threads.
// ---------------------------------------------------------------------------
__global__ void vq_finalize_kernel(float* __restrict__ out, int write_scalars) {
    __shared__ float red[512];
    int t = threadIdx.x;

    float s = g_loss_part[t] + g_loss_part[t + 512];
    red[t] = s;
    __syncthreads();
#pragma unroll
    for (int st = 256; st > 0; st >>= 1) {
        if (t < st) red[t] += red[t + st];
        __syncthreads();
    }
    float loss = red[0] / (float)NTD;

    float p = (float)g_hist[t] * (1.0f / (float)NT);
    red[t] = p * logf(p + 1e-10f);
    __syncthreads();
#pragma unroll
    for (int st = 256; st > 0; st >>= 1) {
        if (t < st) red[t] += red[t + st];
        __syncthreads();
    }
    if (t == 0 && write_scalars) {
        out[NTD]     = loss;
        out[NTD + 1] = expf(-red[0]);
    }
}

// ---------------------------------------------------------------------------
extern "C" void kernel_launch(void* const* d_in, const int* in_sizes, int n_in,
                              void* d_out, int out_size) {
    const float* x   = (const float*)d_in[0];      // (16,4096,256) fp32
    const float* emb = (const float*)d_in[1];      // (512,256) fp32
    float* out = (float*)d_out;

    cudaFuncSetAttribute(vq_main_kernel,
                         cudaFuncAttributeMaxDynamicSharedMemorySize, SMEM_BYTES);

    vq_prep_kernel<<<MM, 256>>>(emb);
    vq_main_kernel<<<NBLOCKS, 256, SMEM_BYTES>>>(x, emb, out);
    int write_scalars = (out_size >= NTD + 2) ? 1 : 0;
    vq_finalize_kernel<<<1, 512>>>(out, write_scalars);
}